// round 1
// baseline (speedup 1.0000x reference)
#include <cuda_runtime.h>

// Problem constants (from reference)
#define NU   100000
#define NI   50000
#define NN   150000            // NU + NI
#define DD   64
#define NNZV 3200000           // 2 * 1,600,000 (symmetrized)
#define BB   4096
#define SCAN_BS 1024
#define NB1  ((NN + SCAN_BS - 1) / SCAN_BS)   // 147

// Scratch (device globals: allocation-free per harness rules)
__device__ float g_x[NN * DD];       // 38.4 MB
__device__ float g_y[NN * DD];       // 38.4 MB
__device__ float g_acc[NN * DD];     // 38.4 MB
__device__ int   g_cnt[NN];          // histogram, then scatter cursors
__device__ int   g_rowptr[NN + 1];
__device__ int   g_cols[NNZV];
__device__ float g_vals[NNZV];
__device__ int   g_bsum[NB1];

// ---------------------------------------------------------------------------
// Init: x = concat(user_emb, item_emb); acc = x; zero histogram
// ---------------------------------------------------------------------------
__global__ void k_init(const float* __restrict__ ue, const float* __restrict__ ie) {
    int stride = gridDim.x * blockDim.x;
    int tid = blockIdx.x * blockDim.x + threadIdx.x;
    for (int i = tid; i < NN * DD; i += stride) {
        float v = (i < NU * DD) ? ue[i] : ie[i - NU * DD];
        g_x[i] = v;
        g_acc[i] = v;
    }
    for (int i = tid; i < NN; i += stride) g_cnt[i] = 0;
}

// ---------------------------------------------------------------------------
// CSR build: histogram -> exclusive scan (3 kernels) -> scatter
// ---------------------------------------------------------------------------
__global__ void k_hist(const int* __restrict__ rows) {
    int stride = gridDim.x * blockDim.x;
    for (int e = blockIdx.x * blockDim.x + threadIdx.x; e < NNZV; e += stride)
        atomicAdd(&g_cnt[rows[e]], 1);
}

__global__ void k_scan1() {   // per-block exclusive scan + block totals
    __shared__ int sh[SCAN_BS];
    int t = threadIdx.x;
    int i = blockIdx.x * SCAN_BS + t;
    int v = (i < NN) ? g_cnt[i] : 0;
    sh[t] = v;
    __syncthreads();
    for (int off = 1; off < SCAN_BS; off <<= 1) {
        int y = (t >= off) ? sh[t - off] : 0;
        __syncthreads();
        sh[t] += y;
        __syncthreads();
    }
    if (i < NN) g_rowptr[i] = sh[t] - v;          // exclusive, pre-offset
    if (t == SCAN_BS - 1) g_bsum[blockIdx.x] = sh[t];
}

__global__ void k_scan2() {   // tiny: scan 147 block sums
    if (blockIdx.x == 0 && threadIdx.x == 0) {
        int a = 0;
        for (int b = 0; b < NB1; b++) { int t = g_bsum[b]; g_bsum[b] = a; a += t; }
    }
}

__global__ void k_scan3() {   // add block offsets; init scatter cursors
    int stride = gridDim.x * blockDim.x;
    for (int i = blockIdx.x * blockDim.x + threadIdx.x; i < NN; i += stride) {
        int val = g_rowptr[i] + g_bsum[i >> 10];
        g_rowptr[i] = val;
        g_cnt[i]    = val;    // running write cursor for scatter
    }
    if (blockIdx.x == 0 && threadIdx.x == 0) g_rowptr[NN] = NNZV;
}

__global__ void k_scatter(const int* __restrict__ rows, const int* __restrict__ cols,
                          const float* __restrict__ vals) {
    int stride = gridDim.x * blockDim.x;
    for (int e = blockIdx.x * blockDim.x + threadIdx.x; e < NNZV; e += stride) {
        int r = rows[e];
        int p = atomicAdd(&g_cnt[r], 1);
        g_cols[p] = cols[e];
        g_vals[p] = vals[e];
    }
}

// ---------------------------------------------------------------------------
// SpMM: one warp per row. Lanes hold D=64 as float2 accumulators.
// Edges fetched 32-at-a-time coalesced, broadcast via shfl.
// Epilogue fuses acc += y. flip selects ping-pong direction.
// ---------------------------------------------------------------------------
__global__ void k_spmm(int flip) {
    const float2* __restrict__ x2 = (const float2*)(flip ? g_y : g_x);
    float2*       __restrict__ y2 = (float2*)      (flip ? g_x : g_y);

    int warp = (blockIdx.x * blockDim.x + threadIdx.x) >> 5;
    if (warp >= NN) return;
    int lane = threadIdx.x & 31;

    int s = g_rowptr[warp];
    int e = g_rowptr[warp + 1];

    float ax = 0.f, ay = 0.f;
    for (int p = s; p < e; p += 32) {
        int pi = p + lane;
        int   c = 0;
        float v = 0.f;
        if (pi < e) { c = __ldg(&g_cols[pi]); v = __ldg(&g_vals[pi]); }
#pragma unroll
        for (int j = 0; j < 32; j++) {
            int   cj = __shfl_sync(0xffffffffu, c, j);
            float vj = __shfl_sync(0xffffffffu, v, j);
            if (p + j < e) {                       // uniform guard -> predication
                float2 xv = x2[cj * 32 + lane];    // coalesced 256B per edge
                ax += vj * xv.x;
                ay += vj * xv.y;
            }
        }
    }

    int o = warp * 32 + lane;
    y2[o] = make_float2(ax, ay);
    float2* a2 = (float2*)g_acc;
    float2 av = a2[o];
    av.x += ax;
    av.y += ay;
    a2[o] = av;
}

// ---------------------------------------------------------------------------
// Scorer: warp per (user, item) pair, dot over D=64, scale by 1/16
// ---------------------------------------------------------------------------
__global__ void k_score(const int* __restrict__ uids, const int* __restrict__ iids,
                        float* __restrict__ out) {
    int warp = (blockIdx.x * blockDim.x + threadIdx.x) >> 5;
    if (warp >= BB) return;
    int lane = threadIdx.x & 31;
    int u  = uids[warp];
    int it = iids[warp];
    const float2* a2 = (const float2*)g_acc;
    float2 ua = a2[u * 32 + lane];
    float2 ia = a2[(NU + it) * 32 + lane];
    float sres = ua.x * ia.x + ua.y * ia.y;
#pragma unroll
    for (int o = 16; o; o >>= 1) sres += __shfl_xor_sync(0xffffffffu, sres, o);
    if (lane == 0) out[warp] = sres * 0.0625f;   // 1/(L+1)^2 = 1/16
}

// ---------------------------------------------------------------------------
extern "C" void kernel_launch(void* const* d_in, const int* in_sizes, int n_in,
                              void* d_out, int out_size) {
    const float* ue   = (const float*)d_in[0];   // user_emb [100000,64]
    const float* ie   = (const float*)d_in[1];   // item_emb [50000,64]
    const float* vals = (const float*)d_in[2];   // adj_vals [3.2M]
    const int*   rows = (const int*)  d_in[3];   // adj_rows [3.2M]
    const int*   cols = (const int*)  d_in[4];   // adj_cols [3.2M]
    const int*   uids = (const int*)  d_in[5];   // user_ids [4096]
    const int*   iids = (const int*)  d_in[6];   // item_ids [4096]
    float*       out  = (float*)d_out;           // scores [4096]

    k_init   <<< 2048, 256 >>>(ue, ie);
    k_hist   <<< 2048, 256 >>>(rows);
    k_scan1  <<< NB1, SCAN_BS >>>();
    k_scan2  <<< 1, 32 >>>();
    k_scan3  <<< 592, 256 >>>();
    k_scatter<<< 2048, 256 >>>(rows, cols, vals);

    const int spmm_blocks = (NN * 32 + 255) / 256;   // warp per row
    k_spmm<<< spmm_blocks, 256 >>>(0);   // x -> y
    k_spmm<<< spmm_blocks, 256 >>>(1);   // y -> x
    k_spmm<<< spmm_blocks, 256 >>>(0);   // x -> y

    k_score<<< (BB * 32 + 255) / 256, 256 >>>(uids, iids, out);
}